// round 1
// baseline (speedup 1.0000x reference)
#include <cuda_runtime.h>
#include <math.h>
#include <float.h>
#include <stdint.h>

// Problem constants
#define Bn 32
#define Mn 384
#define Nn 128
#define Cn 92

static __device__ __constant__ float kCOST_IOU = 2.0f;
static __device__ __constant__ float kCOST_L1  = 5.0f;
static __device__ __constant__ float kCOST_CAT = 1.0f;
static __device__ __constant__ float kLOSS_CAT = 1.0f;
static __device__ __constant__ float kEPS      = 1e-7f;

// Scratch (device globals: allocation-free)
__device__ float  g_cost[(size_t)Bn * Nn * Mn];   // [b][n][m]
__device__ float2 g_stats[Bn * Mn];               // (max, sumexp) per (b,m)
__device__ float4 g_pxy[Bn * Mn];                 // pred xyxy
__device__ float4 g_txy[Bn * Nn];                 // targ xyxy
__device__ int    g_assign[Bn * Nn];
__device__ float  g_loss[Bn];

// ---------------------------------------------------------------------------
// Kernel 1: per-(b,m) softmax stats + pred xyxy; per-(b,n) targ xyxy
// ---------------------------------------------------------------------------
__global__ void prep_kernel(const float* __restrict__ pred_cat,
                            const float* __restrict__ pred_bbox,
                            const float* __restrict__ targ_bbox) {
    int t = blockIdx.x * blockDim.x + threadIdx.x;
    if (t < Bn * Mn) {
        const float* row = pred_cat + (size_t)t * Cn;
        float mx = -FLT_MAX;
        for (int c = 0; c < Cn; c++) mx = fmaxf(mx, row[c]);
        float s = 0.0f;
        for (int c = 0; c < Cn; c++) s += expf(row[c] - mx);
        g_stats[t] = make_float2(mx, s);
        float cx = pred_bbox[t * 4 + 0], cy = pred_bbox[t * 4 + 1];
        float w  = pred_bbox[t * 4 + 2], h  = pred_bbox[t * 4 + 3];
        g_pxy[t] = make_float4(cx - 0.5f * w, cy - 0.5f * h,
                               cx + 0.5f * w, cy + 0.5f * h);
    } else if (t < Bn * Mn + Bn * Nn) {
        int u = t - Bn * Mn;
        float cx = targ_bbox[u * 4 + 0], cy = targ_bbox[u * 4 + 1];
        float w  = targ_bbox[u * 4 + 2], h  = targ_bbox[u * 4 + 3];
        g_txy[u] = make_float4(cx - 0.5f * w, cy - 0.5f * h,
                               cx + 0.5f * w, cy + 0.5f * h);
    }
}

// GIoU-loss + L1 helper (matches reference formula order)
__device__ __forceinline__ float bbox_pair_cost(float4 p, float4 t) {
    float ix1 = fmaxf(p.x, t.x), iy1 = fmaxf(p.y, t.y);
    float ix2 = fminf(p.z, t.z), iy2 = fminf(p.w, t.w);
    float inter = fmaxf(ix2 - ix1, 0.0f) * fmaxf(iy2 - iy1, 0.0f);
    float ap = (p.z - p.x) * (p.w - p.y);
    float at = (t.z - t.x) * (t.w - t.y);
    float un = ap + at - inter;
    float iou = inter / (un + kEPS);
    float cx1 = fminf(p.x, t.x), cy1 = fminf(p.y, t.y);
    float cx2 = fmaxf(p.z, t.z), cy2 = fmaxf(p.w, t.w);
    float ac = (cx2 - cx1) * (cy2 - cy1);
    float giou = iou - (ac - un) / (ac + kEPS);
    float gl = 1.0f - giou;
    float l1 = (fabsf(p.x - t.x) + fabsf(p.y - t.y) +
                fabsf(p.z - t.z) + fabsf(p.w - t.w)) * 0.25f;
    return kCOST_IOU * gl + kCOST_L1 * l1;
}

// ---------------------------------------------------------------------------
// Kernel 2: cost matrix, one block per (b,n), thread per m (coalesced writes)
// ---------------------------------------------------------------------------
__global__ __launch_bounds__(Mn) void cost_kernel(const float* __restrict__ pred_cat,
                                                  const int* __restrict__ targ_cat) {
    int b = blockIdx.y, n = blockIdx.x, m = threadIdx.x;
    int tc = targ_cat[b * Nn + n];
    float4 t4 = g_txy[b * Nn + n];
    float maskf = (tc != 0) ? 1.0f : 0.0f;

    float2 st = g_stats[b * Mn + m];
    float logit = pred_cat[((size_t)(b * Mn + m)) * Cn + tc];
    float prob = expf(logit - st.x) / st.y;
    float cat = kCOST_CAT * (1.0f - prob);

    float bb = bbox_pair_cost(g_pxy[b * Mn + m], t4);
    g_cost[((size_t)(b * Nn + n)) * Mn + m] = cat + bb * maskf;
}

// ---------------------------------------------------------------------------
// Kernel 3: Hungarian (JV), one block per batch, float64 duals to match numpy
// ---------------------------------------------------------------------------
#define CS_BYTES   (Nn * Mn * 4)            // 196608
#define OFF_U      (CS_BYTES)               // double[Nn+1]
#define OFF_V      (OFF_U + (Nn + 1) * 8)   // double[Mn+1]
#define OFF_MINV   (OFF_V + (Mn + 1) * 8)   // double[Mn+1]
#define OFF_P      (OFF_MINV + (Mn + 1) * 8) // int[Mn+1]
#define OFF_WAY    (OFF_P + (Mn + 1) * 4)
#define OFF_USED   (OFF_WAY + (Mn + 1) * 4)
#define OFF_WVAL   (((OFF_USED + (Mn + 1) * 4) + 7) & ~7) // double[12]
#define OFF_WIDX   (OFF_WVAL + 12 * 8)                    // int[12]
#define SMEM_TOTAL (OFF_WIDX + 12 * 4)

__global__ __launch_bounds__(Mn) void hungarian_kernel() {
    int b = blockIdx.x;
    extern __shared__ unsigned char smem[];
    float*  cs   = (float*)smem;
    double* u    = (double*)(smem + OFF_U);
    double* v    = (double*)(smem + OFF_V);
    double* minv = (double*)(smem + OFF_MINV);
    int*    p    = (int*)(smem + OFF_P);
    int*    way  = (int*)(smem + OFF_WAY);
    int*    used = (int*)(smem + OFF_USED);
    double* wval = (double*)(smem + OFF_WVAL);
    int*    widx = (int*)(smem + OFF_WIDX);

    __shared__ int j0_sh, k_sh, done_sh;
    __shared__ double delta_sh;

    int tid = threadIdx.x;
    int wid = tid >> 5, lane = tid & 31;
    const double DINF = (double)INFINITY;

    const float* gc = g_cost + (size_t)b * Nn * Mn;
    for (int idx = tid; idx < Nn * Mn; idx += Mn) cs[idx] = gc[idx];
    for (int j = tid; j <= Mn; j += Mn) { v[j] = 0.0; p[j] = 0; }
    if (tid <= Nn) u[tid] = 0.0;
    __syncthreads();

    for (int i = 1; i <= Nn; i++) {
        {
            int j = tid + 1;
            minv[j] = DINF;
            used[j] = 0;
            if (tid == 0) { used[0] = 0; p[0] = i; j0_sh = 0; }
        }
        __syncthreads();

        while (true) {
            if (tid == 0) used[j0_sh] = 1;
            __syncthreads();
            int j0 = j0_sh;
            int i0 = p[j0];
            double ui0 = u[i0];

            int j = tid + 1;
            bool fr = (used[j] == 0);
            double mv;
            if (fr) {
                double cur = (double)cs[(i0 - 1) * Mn + (j - 1)] - ui0 - v[j];
                if (cur < minv[j]) { minv[j] = cur; way[j] = j0; }
                mv = minv[j];
            } else {
                mv = DINF;
            }
            int mi = j;

            // warp min-reduce (value, then lowest index on ties — numpy argmin)
            #pragma unroll
            for (int off = 16; off; off >>= 1) {
                double ov = __shfl_down_sync(0xffffffffu, mv, off);
                int    oi = __shfl_down_sync(0xffffffffu, mi, off);
                if (ov < mv || (ov == mv && oi < mi)) { mv = ov; mi = oi; }
            }
            if (lane == 0) { wval[wid] = mv; widx[wid] = mi; }
            __syncthreads();
            if (wid == 0) {
                double rv = (lane < 12) ? wval[lane] : DINF;
                int    ri = (lane < 12) ? widx[lane] : 0x7fffffff;
                #pragma unroll
                for (int off = 16; off; off >>= 1) {
                    double ov = __shfl_down_sync(0xffffffffu, rv, off);
                    int    oi = __shfl_down_sync(0xffffffffu, ri, off);
                    if (ov < rv || (ov == rv && oi < ri)) { rv = ov; ri = oi; }
                }
                if (lane == 0) { delta_sh = rv; k_sh = ri; }
            }
            __syncthreads();

            double delta = delta_sh;
            int k = k_sh;
            if (fr) {
                minv[j] -= delta;
            } else {
                u[p[j]] += delta;   // p distinct among used columns
                v[j]    -= delta;
            }
            if (tid == 0) {
                u[p[0]] += delta;   // column 0 always used
                v[0]    -= delta;
                j0_sh = k;
                done_sh = (p[k] == 0);
            }
            __syncthreads();
            if (done_sh) break;
        }

        if (tid == 0) {
            int j0 = j0_sh;
            while (j0) { int j1 = way[j0]; p[j0] = p[j1]; j0 = j1; }
        }
        __syncthreads();
    }

    {
        int j = tid + 1;
        int pi = p[j];
        if (pi > 0) g_assign[b * Nn + (pi - 1)] = j - 1;
    }
}

// ---------------------------------------------------------------------------
// Kernel 4: per-batch loss
// ---------------------------------------------------------------------------
__global__ __launch_bounds__(Nn) void loss_kernel(const float* __restrict__ pred_cat,
                                                  const int* __restrict__ targ_cat) {
    int b = blockIdx.x, n = threadIdx.x;
    int a  = g_assign[b * Nn + n];
    int tc = targ_cat[b * Nn + n];

    float2 st = g_stats[b * Mn + a];
    float logit = pred_cat[((size_t)(b * Mn + a)) * Cn + tc];
    float ce = -(logit - st.x - logf(st.y));

    float bl = bbox_pair_cost(g_pxy[b * Mn + a], g_txy[b * Nn + n]);
    float mk = (tc != 0) ? 1.0f : 0.0f;
    bl *= mk;

    // reduce ce, bl, mk over 128 threads
    float s_ce = ce, s_bl = bl, s_mk = mk;
    #pragma unroll
    for (int off = 16; off; off >>= 1) {
        s_ce += __shfl_down_sync(0xffffffffu, s_ce, off);
        s_bl += __shfl_down_sync(0xffffffffu, s_bl, off);
        s_mk += __shfl_down_sync(0xffffffffu, s_mk, off);
    }
    __shared__ float r1[4], r2[4], r3[4];
    int wid = n >> 5, lane = n & 31;
    if (lane == 0) { r1[wid] = s_ce; r2[wid] = s_bl; r3[wid] = s_mk; }
    __syncthreads();
    if (n == 0) {
        float ce_sum = r1[0] + r1[1] + r1[2] + r1[3];
        float bl_sum = r2[0] + r2[1] + r2[2] + r2[3];
        float mk_sum = r3[0] + r3[1] + r3[2] + r3[3];
        g_loss[b] = (ce_sum / (float)Nn) * kLOSS_CAT + bl_sum / (mk_sum + kEPS);
    }
}

// ---------------------------------------------------------------------------
// Kernel 5: finalize output (mode depends on out_size)
// ---------------------------------------------------------------------------
__global__ void finalize_kernel(float* __restrict__ out, int mode) {
    int t = blockIdx.x * blockDim.x + threadIdx.x;
    if (mode == 0) {  // [loss, assign...]
        if (t == 0) {
            float s = 0.0f;
            for (int b = 0; b < Bn; b++) s += g_loss[b];
            out[0] = s / (float)Bn;
        }
        if (t < Bn * Nn) out[1 + t] = (float)g_assign[t];
    } else if (mode == 1) {  // assign only
        if (t < Bn * Nn) out[t] = (float)g_assign[t];
    } else {  // loss only
        if (t == 0) {
            float s = 0.0f;
            for (int b = 0; b < Bn; b++) s += g_loss[b];
            out[0] = s / (float)Bn;
        }
    }
}

// ---------------------------------------------------------------------------
extern "C" void kernel_launch(void* const* d_in, const int* in_sizes, int n_in,
                              void* d_out, int out_size) {
    const float* pred_cat  = (const float*)d_in[0];
    const float* pred_bbox = (const float*)d_in[1];
    const int*   targ_cat  = (const int*)d_in[2];
    const float* targ_bbox = (const float*)d_in[3];
    float* out = (float*)d_out;

    int tot = Bn * Mn + Bn * Nn;
    prep_kernel<<<(tot + 127) / 128, 128>>>(pred_cat, pred_bbox, targ_bbox);

    dim3 gc(Nn, Bn);
    cost_kernel<<<gc, Mn>>>(pred_cat, targ_cat);

    cudaFuncSetAttribute(hungarian_kernel,
                         cudaFuncAttributeMaxDynamicSharedMemorySize, SMEM_TOTAL);
    hungarian_kernel<<<Bn, Mn, SMEM_TOTAL>>>();

    loss_kernel<<<Bn, Nn>>>(pred_cat, targ_cat);

    int mode;
    if (out_size == Bn * Nn + 1)      mode = 0;
    else if (out_size == Bn * Nn)     mode = 1;
    else                              mode = 2;
    finalize_kernel<<<(Bn * Nn + 127) / 128, 128>>>(out, mode);
}